// round 2
// baseline (speedup 1.0000x reference)
#include <cuda_runtime.h>
#include <cstdint>

// CRF loss: mean_b( logZ_b - gold_b )
// B=256, T=1024, C=64 (fixed problem shape)

#define BD 256
#define TD 1024
#define CD 64
#define LOG2E 1.4426950408889634f
#define LN2   0.6931471805599453f

__device__ float g_partial[BD];

__device__ __forceinline__ float fast_exp2(float x) {
    float y; asm("ex2.approx.ftz.f32 %0, %1;" : "=f"(y) : "f"(x)); return y;
}
__device__ __forceinline__ float fast_log2(float x) {
    float y; asm("lg2.approx.ftz.f32 %0, %1;" : "=f"(y) : "f"(x)); return y;
}

__global__ __launch_bounds__(CD, 2)
void crf_forward_kernel(const float* __restrict__ emissions,
                        const float* __restrict__ transitions,
                        const float* __restrict__ start_t,
                        const float* __restrict__ end_t,
                        const int*   __restrict__ tags,
                        const float* __restrict__ mask)
{
    __shared__ float E[CD * CD];              // exp(transitions), row-major
    __shared__ __align__(16) float p[CD];     // exp(score - M)
    __shared__ float swp[2];
    __shared__ float gred[2];
    __shared__ int   cred[2];

    const int b    = blockIdx.x;
    const int j    = threadIdx.x;      // 0..63, owns tag j
    const int w    = j >> 5;
    const int lane = j & 31;

    const float* em = emissions + (size_t)b * TD * CD;
    const int*   tg = tags      + (size_t)b * TD;
    const float* mk = mask      + (size_t)b * TD;

    // ---- build E = exp(transitions) in smem ----
    #pragma unroll 4
    for (int i = 0; i < CD; i++)
        E[i * CD + j] = fast_exp2(transitions[i * CD + j] * LOG2E);

    // ---- gold score (parallel over t) ----
    float gp  = 0.f;
    int   cnt = 0;
    for (int t = j; t < TD; t += CD) {
        float m = mk[t];
        cnt += (int)m;
        if (t >= 1) {
            int tc = tg[t], tp = tg[t - 1];
            gp += m * (em[t * CD + tc] + transitions[tp * CD + tc]);
        }
    }
    #pragma unroll
    for (int off = 16; off; off >>= 1) {
        gp  += __shfl_xor_sync(0xffffffffu, gp,  off);
        cnt += __shfl_xor_sync(0xffffffffu, cnt, off);
    }
    if (lane == 0) { gred[w] = gp; cred[w] = cnt; }

    // ---- forward init (t = 0) ----
    float score = start_t[j] + em[j];

    __syncthreads();   // E visible, gred/cred visible

    float gold = 0.f;
    if (j == 0) {
        int seqlen  = cred[0] + cred[1];
        int lastidx = seqlen - 1; if (lastidx < 0) lastidx = 0;
        int t0 = tg[0], tl = tg[lastidx];
        gold = gred[0] + gred[1] + start_t[t0] + em[t0] + end_t[tl];
    }

    // ---- forward recursion ----
    float emit_next = em[1 * CD + j];   // prefetch t=1
    float mask_next = mk[1];

    for (int t = 1; t < TD; t++) {
        const float emit = emit_next;
        const float mt   = mask_next;
        if (t + 1 < TD) {
            emit_next = em[(t + 1) * CD + j];
            mask_next = mk[t + 1];
        }

        // block max of score (64 threads = 2 warps)
        float m = score;
        #pragma unroll
        for (int off = 16; off; off >>= 1)
            m = fmaxf(m, __shfl_xor_sync(0xffffffffu, m, off));
        if (lane == 0) swp[w] = m;
        __syncthreads();                       // also protects prev-iter p reads
        const float M = fmaxf(swp[0], swp[1]);

        p[j] = fast_exp2((score - M) * LOG2E);
        __syncthreads();

        // s_j = sum_i p[i] * E[i][j]
        float a0 = 0.f, a1 = 0.f, a2 = 0.f, a3 = 0.f;
        #pragma unroll
        for (int i = 0; i < CD; i += 4) {
            float4 pv = *(const float4*)&p[i];
            a0 = fmaf(pv.x, E[(i + 0) * CD + j], a0);
            a1 = fmaf(pv.y, E[(i + 1) * CD + j], a1);
            a2 = fmaf(pv.z, E[(i + 2) * CD + j], a2);
            a3 = fmaf(pv.w, E[(i + 3) * CD + j], a3);
        }
        const float s   = (a0 + a1) + (a2 + a3);
        const float nxt = M + fast_log2(s) * LN2 + emit;
        score = (mt > 0.f) ? nxt : score;
    }

    // ---- final logsumexp(score + end) ----
    float v = score + end_t[j];
    float m = v;
    #pragma unroll
    for (int off = 16; off; off >>= 1)
        m = fmaxf(m, __shfl_xor_sync(0xffffffffu, m, off));
    __syncthreads();                 // last matvec reads done; reuse swp/p
    if (lane == 0) swp[w] = m;
    __syncthreads();
    const float M = fmaxf(swp[0], swp[1]);

    float e = fast_exp2((v - M) * LOG2E);
    #pragma unroll
    for (int off = 16; off; off >>= 1)
        e += __shfl_xor_sync(0xffffffffu, e, off);
    if (lane == 0) p[w] = e;
    __syncthreads();

    if (j == 0) {
        float fwd = M + fast_log2(p[0] + p[1]) * LN2;
        g_partial[b] = fwd - gold;
    }
}

__global__ void crf_reduce_kernel(float* __restrict__ out)
{
    const int j = threadIdx.x;     // 256 threads
    float v = g_partial[j];
    __shared__ float sm[8];
    #pragma unroll
    for (int off = 16; off; off >>= 1)
        v += __shfl_xor_sync(0xffffffffu, v, off);
    if ((j & 31) == 0) sm[j >> 5] = v;
    __syncthreads();
    if (j < 8) {
        v = sm[j];
        #pragma unroll
        for (int off = 4; off; off >>= 1)
            v += __shfl_xor_sync(0x000000ffu, v, off);
        if (j == 0) out[0] = v * (1.0f / BD);
    }
}

extern "C" void kernel_launch(void* const* d_in, const int* in_sizes, int n_in,
                              void* d_out, int out_size)
{
    const float* emissions   = (const float*)d_in[0];
    const float* transitions = (const float*)d_in[1];
    const float* start_t     = (const float*)d_in[2];
    const float* end_t       = (const float*)d_in[3];
    const int*   tags        = (const int*)  d_in[4];
    const float* mask        = (const float*)d_in[5];
    float* out = (float*)d_out;

    crf_forward_kernel<<<BD, CD>>>(emissions, transitions, start_t, end_t, tags, mask);
    crf_reduce_kernel<<<1, BD>>>(out);
}

// round 4
// speedup vs baseline: 1.6354x; 1.6354x over previous
#include <cuda_runtime.h>
#include <cstdint>

// CRF loss: mean_b( logZ_b - gold_b )
// B=256, T=1024, C=64 (fixed problem shape)

#define BD 256
#define TD 1024
#define CD 64
#define LOG2E 1.4426950408889634f
#define LN2   0.6931471805599453f

__device__ float g_partial[BD];

__device__ __forceinline__ float fast_exp2(float x) {
    float y; asm("ex2.approx.ftz.f32 %0, %1;" : "=f"(y) : "f"(x)); return y;
}
__device__ __forceinline__ float fast_log2(float x) {
    float y; asm("lg2.approx.ftz.f32 %0, %1;" : "=f"(y) : "f"(x)); return y;
}

__global__ __launch_bounds__(CD)
void crf_forward_kernel(const float* __restrict__ emissions,
                        const float* __restrict__ transitions,
                        const float* __restrict__ start_t,
                        const float* __restrict__ end_t,
                        const int*   __restrict__ tags,
                        const float* __restrict__ mask)
{
    __shared__ __align__(16) float p[CD];     // exp(score - M)
    __shared__ float Mslot;                   // lagged normalizer (score of tag 0)
    __shared__ float swp[2];
    __shared__ float gred[2];
    __shared__ int   cred[2];

    const int b    = blockIdx.x;
    const int j    = threadIdx.x;      // 0..63, owns tag j
    const int w    = j >> 5;
    const int lane = j & 31;

    const float* em = emissions + (size_t)b * TD * CD;
    const int*   tg = tags      + (size_t)b * TD;
    const float* mk = mask      + (size_t)b * TD;

    // ---- E column j = exp(transitions[:, j]) into registers ----
    float Ec[CD];
    #pragma unroll
    for (int i = 0; i < CD; i++)
        Ec[i] = fast_exp2(transitions[i * CD + j] * LOG2E);

    // ---- gold score (parallel over t) ----
    float gp  = 0.f;
    int   cnt = 0;
    for (int t = j; t < TD; t += CD) {
        float m = mk[t];
        cnt += (int)m;
        if (t >= 1) {
            int tc = tg[t], tp = tg[t - 1];
            gp += m * (em[t * CD + tc] + transitions[tp * CD + tc]);
        }
    }
    #pragma unroll
    for (int off = 16; off; off >>= 1) {
        gp  += __shfl_xor_sync(0xffffffffu, gp,  off);
        cnt += __shfl_xor_sync(0xffffffffu, cnt, off);
    }
    if (lane == 0) { gred[w] = gp; cred[w] = cnt; }

    // ---- forward init (t = 0) ----
    float score = start_t[j] + em[j];
    if (j == 0) Mslot = score;

    __syncthreads();   // Mslot, gred/cred visible

    float gold = 0.f;
    if (j == 0) {
        int seqlen  = cred[0] + cred[1];
        int lastidx = seqlen - 1; if (lastidx < 0) lastidx = 0;
        int t0 = tg[0], tl = tg[lastidx];
        gold = gred[0] + gred[1] + start_t[t0] + em[t0] + end_t[tl];
    }

    // ---- forward recursion ----
    // Normalizer M = score[tag 0] of the previous step (lagged, exact max not
    // needed: |score_j - score_0| stays O(few) << 87, so exp never overflows).
    float emit_next = em[1 * CD + j];   // prefetch t=1
    float mask_next = mk[1];

    for (int t = 1; t < TD; t++) {
        const float emit = emit_next;
        const float mt   = mask_next;
        if (t + 1 < TD) {
            emit_next = em[(t + 1) * CD + j];
            mask_next = mk[t + 1];
        }

        const float M = Mslot;                       // broadcast LDS
        p[j] = fast_exp2((score - M) * LOG2E);
        __syncthreads();                             // p visible; M consumed

        // s_j = sum_i p[i] * E[i][j]   (E in registers, p broadcast from smem)
        float a0 = 0.f, a1 = 0.f, a2 = 0.f, a3 = 0.f;
        float a4 = 0.f, a5 = 0.f, a6 = 0.f, a7 = 0.f;
        #pragma unroll
        for (int i = 0; i < CD; i += 8) {
            float4 pv0 = *(const float4*)&p[i];
            float4 pv1 = *(const float4*)&p[i + 4];
            a0 = fmaf(pv0.x, Ec[i + 0], a0);
            a1 = fmaf(pv0.y, Ec[i + 1], a1);
            a2 = fmaf(pv0.z, Ec[i + 2], a2);
            a3 = fmaf(pv0.w, Ec[i + 3], a3);
            a4 = fmaf(pv1.x, Ec[i + 4], a4);
            a5 = fmaf(pv1.y, Ec[i + 5], a5);
            a6 = fmaf(pv1.z, Ec[i + 6], a6);
            a7 = fmaf(pv1.w, Ec[i + 7], a7);
        }
        const float s   = ((a0 + a1) + (a2 + a3)) + ((a4 + a5) + (a6 + a7));
        const float nxt = M + fast_log2(s) * LN2 + emit;
        score = (mt > 0.f) ? nxt : score;

        if (j == 0) Mslot = score;                   // next step's normalizer
        __syncthreads();                             // Mslot visible; p reads done
    }

    // ---- final logsumexp(score + end) ----
    float v = score + end_t[j];
    float m = v;
    #pragma unroll
    for (int off = 16; off; off >>= 1)
        m = fmaxf(m, __shfl_xor_sync(0xffffffffu, m, off));
    if (lane == 0) swp[w] = m;
    __syncthreads();
    const float M = fmaxf(swp[0], swp[1]);

    float e = fast_exp2((v - M) * LOG2E);
    #pragma unroll
    for (int off = 16; off; off >>= 1)
        e += __shfl_xor_sync(0xffffffffu, e, off);
    if (lane == 0) p[w] = e;
    __syncthreads();

    if (j == 0) {
        float fwd = M + fast_log2(p[0] + p[1]) * LN2;
        g_partial[b] = fwd - gold;
    }
}

__global__ void crf_reduce_kernel(float* __restrict__ out)
{
    const int j = threadIdx.x;     // 256 threads
    float v = g_partial[j];
    __shared__ float sm[8];
    #pragma unroll
    for (int off = 16; off; off >>= 1)
        v += __shfl_xor_sync(0xffffffffu, v, off);
    if ((j & 31) == 0) sm[j >> 5] = v;
    __syncthreads();
    if (j < 8) {
        v = sm[j];
        #pragma unroll
        for (int off = 4; off; off >>= 1)
            v += __shfl_xor_sync(0x000000ffu, v, off);
        if (j == 0) out[0] = v * (1.0f / BD);
    }
}

extern "C" void kernel_launch(void* const* d_in, const int* in_sizes, int n_in,
                              void* d_out, int out_size)
{
    const float* emissions   = (const float*)d_in[0];
    const float* transitions = (const float*)d_in[1];
    const float* start_t     = (const float*)d_in[2];
    const float* end_t       = (const float*)d_in[3];
    const int*   tags        = (const int*)  d_in[4];
    const float* mask        = (const float*)d_in[5];
    float* out = (float*)d_out;

    crf_forward_kernel<<<BD, CD>>>(emissions, transitions, start_t, end_t, tags, mask);
    crf_reduce_kernel<<<1, BD>>>(out);
}

// round 5
// speedup vs baseline: 2.0460x; 1.2511x over previous
#include <cuda_runtime.h>
#include <cstdint>

// CRF loss: mean_b( logZ_b - gold_b )
// B=256, T=1024, C=64 (fixed problem shape)
// Scaled-domain forward algorithm: p_{t+1} = (E^T p_t) ∘ W_t / c_t,
// logZ accumulates log(c_t). Normalizer c_t = p_t[0] (read for free by matvec).

#define BD 256
#define TD 1024
#define CD 64
#define LOG2E 1.4426950408889634f
#define LN2   0.6931471805599453f

__device__ float g_partial[BD];

__device__ __forceinline__ float fast_exp2(float x) {
    float y; asm("ex2.approx.ftz.f32 %0, %1;" : "=f"(y) : "f"(x)); return y;
}
__device__ __forceinline__ float fast_log2(float x) {
    float y; asm("lg2.approx.ftz.f32 %0, %1;" : "=f"(y) : "f"(x)); return y;
}
__device__ __forceinline__ float fast_rcp(float x) {
    float y; asm("rcp.approx.ftz.f32 %0, %1;" : "=f"(y) : "f"(x)); return y;
}

__global__ __launch_bounds__(CD)
void crf_forward_kernel(const float* __restrict__ emissions,
                        const float* __restrict__ transitions,
                        const float* __restrict__ start_t,
                        const float* __restrict__ end_t,
                        const int*   __restrict__ tags,
                        const float* __restrict__ mask)
{
    __shared__ __align__(16) float psh[2][CD];   // double-buffered forward vector
    __shared__ float swp[2];
    __shared__ float gred[2];
    __shared__ int   cred[2];

    const int b    = blockIdx.x;
    const int j    = threadIdx.x;      // 0..63, owns tag j
    const int w    = j >> 5;
    const int lane = j & 31;

    const float* em = emissions + (size_t)b * TD * CD;
    const int*   tg = tags      + (size_t)b * TD;
    const float* mk = mask      + (size_t)b * TD;

    // ---- E column j = exp(transitions[:, j]) into registers ----
    float Ec[CD];
    #pragma unroll
    for (int i = 0; i < CD; i++)
        Ec[i] = fast_exp2(transitions[i * CD + j] * LOG2E);

    // ---- gold score (parallel over t) ----
    float gp  = 0.f;
    int   cnt = 0;
    for (int t = j; t < TD; t += CD) {
        float m = mk[t];
        cnt += (int)m;
        if (t >= 1) {
            int tc = tg[t], tp = tg[t - 1];
            gp += m * (em[t * CD + tc] + transitions[tp * CD + tc]);
        }
    }
    #pragma unroll
    for (int off = 16; off; off >>= 1) {
        gp  += __shfl_xor_sync(0xffffffffu, gp,  off);
        cnt += __shfl_xor_sync(0xffffffffu, cnt, off);
    }
    if (lane == 0) { gred[w] = gp; cred[w] = cnt; }

    // ---- forward init (t = 0): p0 = exp(start + emit0), linear domain ----
    float myp = fast_exp2((start_t[j] + em[j]) * LOG2E);
    psh[0][j] = myp;

    // ---- prefetch ring: W = exp(emit), mask — 4 steps deep ----
    float Wr[4], mr[4];
    #pragma unroll
    for (int t0 = 1; t0 <= 4; t0++) {
        Wr[t0 & 3] = fast_exp2(em[t0 * CD + j] * LOG2E);
        mr[t0 & 3] = mk[t0];
    }

    __syncthreads();   // psh[0], gred/cred visible

    float gold = 0.f;
    if (j == 0) {
        int seqlen  = cred[0] + cred[1];
        int lastidx = seqlen - 1; if (lastidx < 0) lastidx = 0;
        int t0 = tg[0], tl = tg[lastidx];
        gold = gred[0] + gred[1] + start_t[t0] + em[t0] + end_t[tl];
    }

    // ---- forward recursion (linear domain, one barrier/step) ----
    float logAcc = 0.f;   // sum of log2(c_t)
    int   cur    = 0;

    #pragma unroll 4
    for (int t = 1; t < TD; t++) {
        const int   slot = t & 3;
        const float W    = Wr[slot];
        const float mt   = mr[slot];

        // refill ring slot for t+4 (off critical chain)
        const int tp = t + 4;
        if (tp < TD) {
            Wr[slot] = fast_exp2(em[tp * CD + j] * LOG2E);
            mr[slot] = mk[tp];
        }

        const float* pc = psh[cur];
        float4 pv0 = *(const float4*)&pc[0];
        const float c = pv0.x;                 // normalizer = previous p[0]
        const float r = fast_rcp(c);           // runs parallel to FMA tree
        logAcc += fast_log2(c);                // off-chain accumulation

        float a0, a1, a2, a3, a4, a5, a6, a7;
        a0 = pv0.x * Ec[0];
        a1 = pv0.y * Ec[1];
        a2 = pv0.z * Ec[2];
        a3 = pv0.w * Ec[3];
        float4 pv1 = *(const float4*)&pc[4];
        a4 = pv1.x * Ec[4];
        a5 = pv1.y * Ec[5];
        a6 = pv1.z * Ec[6];
        a7 = pv1.w * Ec[7];
        #pragma unroll
        for (int i = 8; i < CD; i += 8) {
            float4 q0 = *(const float4*)&pc[i];
            float4 q1 = *(const float4*)&pc[i + 4];
            a0 = fmaf(q0.x, Ec[i + 0], a0);
            a1 = fmaf(q0.y, Ec[i + 1], a1);
            a2 = fmaf(q0.z, Ec[i + 2], a2);
            a3 = fmaf(q0.w, Ec[i + 3], a3);
            a4 = fmaf(q1.x, Ec[i + 4], a4);
            a5 = fmaf(q1.y, Ec[i + 5], a5);
            a6 = fmaf(q1.z, Ec[i + 6], a6);
            a7 = fmaf(q1.w, Ec[i + 7], a7);
        }
        const float s  = ((a0 + a1) + (a2 + a3)) + ((a4 + a5) + (a6 + a7));
        const float pn = s * W * r;
        // masked step: score unchanged -> p scaled by r (cancels logAcc += log2 c)
        myp = (mt > 0.f) ? pn : myp * r;
        psh[cur ^ 1][j] = myp;
        __syncthreads();        // orders this step's writes/reads vs next step
        cur ^= 1;
    }

    // ---- final: logZ = LN2 * (logAcc + log2(sum_j p[j] * exp(end_j))) ----
    float v = myp * fast_exp2(end_t[j] * LOG2E);
    #pragma unroll
    for (int off = 16; off; off >>= 1)
        v += __shfl_xor_sync(0xffffffffu, v, off);
    if (lane == 0) swp[w] = v;
    __syncthreads();

    if (j == 0) {
        float fwd = (logAcc + fast_log2(swp[0] + swp[1])) * LN2;
        g_partial[b] = fwd - gold;
    }
}

__global__ void crf_reduce_kernel(float* __restrict__ out)
{
    const int j = threadIdx.x;     // 256 threads
    float v = g_partial[j];
    __shared__ float sm[8];
    #pragma unroll
    for (int off = 16; off; off >>= 1)
        v += __shfl_xor_sync(0xffffffffu, v, off);
    if ((j & 31) == 0) sm[j >> 5] = v;
    __syncthreads();
    if (j < 8) {
        v = sm[j];
        #pragma unroll
        for (int off = 4; off; off >>= 1)
            v += __shfl_xor_sync(0x000000ffu, v, off);
        if (j == 0) out[0] = v * (1.0f / BD);
    }
}

extern "C" void kernel_launch(void* const* d_in, const int* in_sizes, int n_in,
                              void* d_out, int out_size)
{
    const float* emissions   = (const float*)d_in[0];
    const float* transitions = (const float*)d_in[1];
    const float* start_t     = (const float*)d_in[2];
    const float* end_t       = (const float*)d_in[3];
    const int*   tags        = (const int*)  d_in[4];
    const float* mask        = (const float*)d_in[5];
    float* out = (float*)d_out;

    crf_forward_kernel<<<BD, CD>>>(emissions, transitions, start_t, end_t, tags, mask);
    crf_reduce_kernel<<<1, BD>>>(out);
}